// round 10
// baseline (speedup 1.0000x reference)
#include <cuda_runtime.h>
#include <cuda_bf16.h>
#include <stdint.h>
#include <math.h>

#define Bn 4
#define Cn 64
#define Hn 128
#define Wn 128
#define On 64
#define HW (Hn * Wn)

typedef unsigned long long ull;

// Scratch (device globals -- no allocations allowed)
__device__ __align__(16) uint32_t g_wBh[9 * 2048];   // deform B [k][o:64][c] bf16-hi, sw128
__device__ __align__(16) uint32_t g_wBl[9 * 2048];   // deform B lo
__device__ __align__(16) uint32_t g_wAh[9 * 1024];   // offs/mask B [k][o:32][c] bf16-hi, sw128
__device__ __align__(16) uint32_t g_wAl[9 * 1024];   // lo

// ---------------------------------------------------------------------------
// helpers
// ---------------------------------------------------------------------------
__device__ __forceinline__ uint32_t cvt_bf16x2(float lo, float hi) {
    uint32_t r;
    asm("cvt.rn.satfinite.bf16x2.f32 %0, %1, %2;" : "=r"(r) : "f"(hi), "f"(lo));
    return r;
}
__device__ __forceinline__ uint32_t smem_u32(const void* p) {
    uint32_t a;
    asm("{ .reg .u64 t; cvta.to.shared.u64 t, %1; cvt.u32.u64 %0, t; }"
        : "=r"(a) : "l"(p));
    return a;
}
__device__ __forceinline__ uint32_t sw128(uint32_t off) {
    return off ^ ((off >> 3) & 0x70);
}
__device__ __forceinline__ uint32_t lds32(uint32_t addr) {
    uint32_t v; asm volatile("ld.shared.b32 %0, [%1];" : "=r"(v) : "r"(addr));
    return v;
}
__device__ __forceinline__ void sts32(uint32_t addr, uint32_t v) {
    asm volatile("st.shared.b32 [%0], %1;" :: "r"(addr), "r"(v) : "memory");
}
// m16n8k16 row.col bf16 -> fp32
__device__ __forceinline__ void mma16816(float* d, const uint32_t* a,
                                         const uint32_t* b) {
    asm volatile(
        "mma.sync.aligned.m16n8k16.row.col.f32.bf16.bf16.f32 "
        "{%0,%1,%2,%3}, {%4,%5,%6,%7}, {%8,%9}, {%0,%1,%2,%3};"
        : "+f"(d[0]), "+f"(d[1]), "+f"(d[2]), "+f"(d[3])
        : "r"(a[0]), "r"(a[1]), "r"(a[2]), "r"(a[3]), "r"(b[0]), "r"(b[1]));
}
// split f32 pair -> (hi bf16x2, lo bf16x2)
__device__ __forceinline__ void split2(float v0, float v1,
                                       uint32_t& hw, uint32_t& lw) {
    hw = cvt_bf16x2(v0, v1);
    float h0 = __uint_as_float(hw << 16);
    float h1 = __uint_as_float(hw & 0xFFFF0000u);
    lw = cvt_bf16x2(v0 - h0, v1 - h1);
}

// ---------------------------------------------------------------------------
// Kernel P: pre-split / pre-swizzle both weight sets.
//   idx < 18432 : deform_w  -> g_wBh/g_wBl  [k][o:64][c]
//   else        : offset_w+mask_w (27 rows, pad to 32) -> g_wAh/g_wAl
// ---------------------------------------------------------------------------
__global__ void prep_w_kernel(const float* __restrict__ dw,
                              const float* __restrict__ ow,
                              const float* __restrict__ mw) {
    int idx = blockIdx.x * blockDim.x + threadIdx.x;
    if (idx < 9 * 64 * 32) {
        int cp = idx & 31;
        int o  = (idx >> 5) & 63;
        int k  = idx >> 11;
        int c0 = cp * 2;
        float w0 = dw[(o * Cn + c0) * 9 + k];
        float w1 = dw[(o * Cn + c0 + 1) * 9 + k];
        uint32_t hw, lw; split2(w0, w1, hw, lw);
        uint32_t off = sw128((uint32_t)(o * 128 + cp * 4));
        g_wBh[k * 2048 + off / 4] = hw;
        g_wBl[k * 2048 + off / 4] = lw;
    } else if (idx < 9 * 64 * 32 + 9 * 32 * 32) {
        int t = idx - 9 * 64 * 32;
        int cp = t & 31;
        int o  = (t >> 5) & 31;
        int k  = t >> 10;
        int c0 = cp * 2;
        float w0 = 0.f, w1 = 0.f;
        if (o < 18) {
            w0 = ow[(o * Cn + c0) * 9 + k];
            w1 = ow[(o * Cn + c0 + 1) * 9 + k];
        } else if (o < 27) {
            w0 = mw[((o - 18) * Cn + c0) * 9 + k];
            w1 = mw[((o - 18) * Cn + c0 + 1) * 9 + k];
        }
        uint32_t hw, lw; split2(w0, w1, hw, lw);
        uint32_t off = sw128((uint32_t)(o * 128 + cp * 4));
        g_wAh[k * 1024 + off / 4] = hw;
        g_wAl[k * 1024 + off / 4] = lw;
    }
}

// ---------------------------------------------------------------------------
// Fused kernel: one block per (b, h) row, 128 threads.
//   Phase 1: offset(18)+mask(9) conv via split-bf16 HMMA (M=128,N=32,K=576)
//            -> bias/sigmoid -> smem S_OFF[32][128].
//   Phase 2: deformable conv via split-bf16 HMMA (M=128,N=64,K=576), offsets
//            read from S_OFF.
// SW128 addressing: addr = row*128 + lr*4 + (colTerm ^ ((row&7)<<4)).
// ---------------------------------------------------------------------------
#define S_AH  0
#define S_AL  16384
#define S_BH  32768
#define S_BL  40960
#define S_OFF 49152
#define S_TOT 65536

__global__ __launch_bounds__(128) void fused_kernel(
    const float* __restrict__ x,
    const float* __restrict__ offset_b,
    const float* __restrict__ mask_b,
    const float* __restrict__ deform_b,
    float* __restrict__ out)
{
    extern __shared__ char smem[];
    const uint32_t sb = smem_u32(smem);
    const int tid  = threadIdx.x;
    const int lane = tid & 31;
    const int wrp  = tid >> 5;
    const int h = blockIdx.x;
    const int b = blockIdx.y;

    const float* xb = x + (size_t)b * Cn * HW;

    const int lq = lane >> 2;            // 0..7
    const int lr = lane & 3;             // 0..3
    const uint32_t swz = ((uint32_t)lq << 4);
    uint32_t aBase[2][2];
#pragma unroll
    for (int mt = 0; mt < 2; ++mt)
#pragma unroll
        for (int rh = 0; rh < 2; ++rh) {
            uint32_t row = wrp * 32 + mt * 16 + rh * 8 + lq;
            aBase[mt][rh] = row * 128 + lr * 4;
        }
    const uint32_t bBase0 = (uint32_t)lq * 128 + lr * 4;

    // ======================= Phase 1: offset/mask conv ======================
    {
        float doff[2][4][4];
#pragma unroll
        for (int mt = 0; mt < 2; ++mt)
#pragma unroll
            for (int nt = 0; nt < 4; ++nt)
#pragma unroll
                for (int i = 0; i < 4; ++i) doff[mt][nt][i] = 0.f;

        for (int k = 0; k < 9; ++k) {
            __syncthreads();
            // B tiles: 4KB hi + 4KB lo
            {
                const float4* sh = reinterpret_cast<const float4*>(g_wAh + k * 1024);
                const float4* sl = reinterpret_cast<const float4*>(g_wAl + k * 1024);
                float4* dh = reinterpret_cast<float4*>(smem + S_BH);
                float4* dl = reinterpret_cast<float4*>(smem + S_BL);
#pragma unroll
                for (int s = tid; s < 256; s += 128) { dh[s] = sh[s]; dl[s] = sl[s]; }
            }
            // A tile: shifted patch value for pixel tid, all 64 channels
            int y = h + k / 3 - 1;
            int xc = tid + k % 3 - 1;
            bool ok = (y >= 0) && (y < Hn) && (xc >= 0) && (xc < Wn);
            const float* xp = xb + y * Wn + xc;
            const uint32_t rowoff = (uint32_t)(tid * 128);
#pragma unroll 4
            for (int cp = 0; cp < 32; ++cp) {
                float v0 = ok ? __ldg(xp + (2 * cp) * HW) : 0.f;
                float v1 = ok ? __ldg(xp + (2 * cp + 1) * HW) : 0.f;
                uint32_t hw, lw; split2(v0, v1, hw, lw);
                uint32_t off = sw128(rowoff + cp * 4);
                sts32(sb + S_AH + off, hw);
                sts32(sb + S_AL + off, lw);
            }
            __syncthreads();
            // MMA: 4 k16-steps, 4 n-tiles
#pragma unroll
            for (int s = 0; s < 4; ++s) {
                const uint32_t c0 = ((uint32_t)(s * 32)) ^ swz;
                const uint32_t c1 = ((uint32_t)(s * 32 + 16)) ^ swz;
                uint32_t ah[2][4], al[2][4];
#pragma unroll
                for (int mt = 0; mt < 2; ++mt) {
                    ah[mt][0] = lds32(sb + S_AH + aBase[mt][0] + c0);
                    ah[mt][1] = lds32(sb + S_AH + aBase[mt][1] + c0);
                    ah[mt][2] = lds32(sb + S_AH + aBase[mt][0] + c1);
                    ah[mt][3] = lds32(sb + S_AH + aBase[mt][1] + c1);
                    al[mt][0] = lds32(sb + S_AL + aBase[mt][0] + c0);
                    al[mt][1] = lds32(sb + S_AL + aBase[mt][1] + c0);
                    al[mt][2] = lds32(sb + S_AL + aBase[mt][0] + c1);
                    al[mt][3] = lds32(sb + S_AL + aBase[mt][1] + c1);
                }
#pragma unroll
                for (int nt = 0; nt < 4; ++nt) {
                    const uint32_t bo = bBase0 + (uint32_t)(nt * 1024);
                    uint32_t bh[2], bl[2];
                    bh[0] = lds32(sb + S_BH + bo + c0);
                    bh[1] = lds32(sb + S_BH + bo + c1);
                    bl[0] = lds32(sb + S_BL + bo + c0);
                    bl[1] = lds32(sb + S_BL + bo + c1);
#pragma unroll
                    for (int mt = 0; mt < 2; ++mt) {
                        mma16816(doff[mt][nt], ah[mt], bh);
                        mma16816(doff[mt][nt], al[mt], bh);
                        mma16816(doff[mt][nt], ah[mt], bl);
                    }
                }
            }
        }
        __syncthreads();   // all B reads done before reusing nothing; order fence
        // Epilogue: bias + sigmoid -> S_OFF[32][128]
        float* offs = reinterpret_cast<float*>(smem + S_OFF);
#pragma unroll
        for (int nt = 0; nt < 4; ++nt) {
            int o0 = nt * 8 + lr * 2;
#pragma unroll
            for (int oi = 0; oi < 2; ++oi) {
                int o = o0 + oi;
                float bias = 0.f; bool sig = false;
                if (o < 18) bias = __ldg(offset_b + o);
                else if (o < 27) { bias = __ldg(mask_b + o - 18); sig = true; }
#pragma unroll
                for (int mt = 0; mt < 2; ++mt) {
                    int px0 = wrp * 32 + mt * 16 + lq;
#pragma unroll
                    for (int ri = 0; ri < 2; ++ri) {
                        float v = doff[mt][nt][ri * 2 + oi] + bias;
                        if (sig) v = 1.f / (1.f + __expf(-v));
                        offs[o * 128 + px0 + ri * 8] = v;
                    }
                }
            }
        }
    }
    // (phase-2 loop-top __syncthreads makes offs visible to all)

    // ========================= Phase 2: deform conv =========================
    float d[2][8][4];
#pragma unroll
    for (int mt = 0; mt < 2; ++mt)
#pragma unroll
        for (int nt = 0; nt < 8; ++nt)
#pragma unroll
            for (int i = 0; i < 4; ++i) d[mt][nt][i] = 0.f;

    const float* offs = reinterpret_cast<const float*>(smem + S_OFF);

    for (int k = 0; k < 9; ++k) {
        __syncthreads();   // prev tap MMA done; also fences phase-1 epilogue

        // copy pre-swizzled B tiles (8KB hi + 8KB lo)
        {
            const float4* sh = reinterpret_cast<const float4*>(g_wBh + k * 2048);
            const float4* sl = reinterpret_cast<const float4*>(g_wBl + k * 2048);
            float4* dh = reinterpret_cast<float4*>(smem + S_BH);
            float4* dl = reinterpret_cast<float4*>(smem + S_BL);
#pragma unroll
            for (int s = tid; s < 512; s += 128) { dh[s] = sh[s]; dl[s] = sl[s]; }
        }

        // bilinear setup for pixel `tid` of row h (offsets from smem)
        float dy = offs[(2 * k) * 128 + tid];
        float dx = offs[(2 * k + 1) * 128 + tid];
        float m  = offs[(18 + k) * 128 + tid];

        float py = dy + (float)(k / 3 + h - 1);
        float px = dx + (float)(k % 3 + tid - 1);
        float y0f = floorf(py), x0f = floorf(px);
        float fy = py - y0f, fx = px - x0f;
        int y0 = (int)y0f, x0 = (int)x0f;
        int y1 = y0 + 1, x1 = x0 + 1;
        float wy0 = 1.f - fy, wx0 = 1.f - fx;
        float w00 = wy0 * wx0 * m;
        float w01 = wy0 * fx  * m;
        float w10 = fy  * wx0 * m;
        float w11 = fy  * fx  * m;
        bool vy0 = (y0 >= 0) && (y0 < Hn);
        bool vy1 = (y1 >= 0) && (y1 < Hn);
        bool vx0 = (x0 >= 0) && (x0 < Wn);
        bool vx1 = (x1 >= 0) && (x1 < Wn);
        if (!(vy0 && vx0)) w00 = 0.f;
        if (!(vy0 && vx1)) w01 = 0.f;
        if (!(vy1 && vx0)) w10 = 0.f;
        if (!(vy1 && vx1)) w11 = 0.f;
        int y0c = min(max(y0, 0), Hn - 1), y1c = min(max(y1, 0), Hn - 1);
        int x0c = min(max(x0, 0), Wn - 1), x1c = min(max(x1, 0), Wn - 1);
        int i00 = y0c * Wn + x0c, i01 = y0c * Wn + x1c;
        int i10 = y1c * Wn + x0c, i11 = y1c * Wn + x1c;

        // gather + split into A_hi/A_lo (row = pixel tid, col pair cp)
        const uint32_t rowoff = (uint32_t)(tid * 128);
#pragma unroll 4
        for (int cp = 0; cp < 32; ++cp) {
            const float* xc0 = xb + (2 * cp) * HW;
            const float* xc1 = xc0 + HW;
            float v0 = w00 * __ldg(xc0 + i00) + w01 * __ldg(xc0 + i01)
                     + w10 * __ldg(xc0 + i10) + w11 * __ldg(xc0 + i11);
            float v1 = w00 * __ldg(xc1 + i00) + w01 * __ldg(xc1 + i01)
                     + w10 * __ldg(xc1 + i10) + w11 * __ldg(xc1 + i11);
            uint32_t hw, lw; split2(v0, v1, hw, lw);
            uint32_t off = sw128(rowoff + cp * 4);
            sts32(sb + S_AH + off, hw);
            sts32(sb + S_AL + off, lw);
        }
        __syncthreads();

        // MMA phase: 4 k16-steps, 8 n-tiles
#pragma unroll
        for (int s = 0; s < 4; ++s) {
            const uint32_t c0 = ((uint32_t)(s * 32)) ^ swz;
            const uint32_t c1 = ((uint32_t)(s * 32 + 16)) ^ swz;
            uint32_t ah[2][4], al[2][4];
#pragma unroll
            for (int mt = 0; mt < 2; ++mt) {
                ah[mt][0] = lds32(sb + S_AH + aBase[mt][0] + c0);
                ah[mt][1] = lds32(sb + S_AH + aBase[mt][1] + c0);
                ah[mt][2] = lds32(sb + S_AH + aBase[mt][0] + c1);
                ah[mt][3] = lds32(sb + S_AH + aBase[mt][1] + c1);
                al[mt][0] = lds32(sb + S_AL + aBase[mt][0] + c0);
                al[mt][1] = lds32(sb + S_AL + aBase[mt][1] + c0);
                al[mt][2] = lds32(sb + S_AL + aBase[mt][0] + c1);
                al[mt][3] = lds32(sb + S_AL + aBase[mt][1] + c1);
            }
#pragma unroll
            for (int nt = 0; nt < 8; ++nt) {
                const uint32_t bo = bBase0 + (uint32_t)(nt * 1024);
                uint32_t bh[2], bl[2];
                bh[0] = lds32(sb + S_BH + bo + c0);
                bh[1] = lds32(sb + S_BH + bo + c1);
                bl[0] = lds32(sb + S_BL + bo + c0);
                bl[1] = lds32(sb + S_BL + bo + c1);
#pragma unroll
                for (int mt = 0; mt < 2; ++mt) {
                    mma16816(d[mt][nt], ah[mt], bh);
                    mma16816(d[mt][nt], al[mt], bh);
                    mma16816(d[mt][nt], ah[mt], bl);
                }
            }
        }
    }

    // epilogue: d[mt][nt][i] -> out[(b*64+o)*HW + h*Wn + px] + bias
#pragma unroll
    for (int nt = 0; nt < 8; ++nt) {
        int o0 = nt * 8 + lr * 2;
        float bb0 = __ldg(deform_b + o0);
        float bb1 = __ldg(deform_b + o0 + 1);
#pragma unroll
        for (int mt = 0; mt < 2; ++mt) {
            int px0 = wrp * 32 + mt * 16 + lq;
            float* o0p = out + ((size_t)(b * On + o0)) * HW + h * Wn;
            float* o1p = o0p + HW;
            o0p[px0]     = d[mt][nt][0] + bb0;
            o1p[px0]     = d[mt][nt][1] + bb1;
            o0p[px0 + 8] = d[mt][nt][2] + bb0;
            o1p[px0 + 8] = d[mt][nt][3] + bb1;
        }
    }
}

// ---------------------------------------------------------------------------
extern "C" void kernel_launch(void* const* d_in, const int* in_sizes, int n_in,
                              void* d_out, int out_size) {
    const float* x        = (const float*)d_in[0];
    const float* offset_w = (const float*)d_in[1];
    const float* offset_b = (const float*)d_in[2];
    const float* mask_w   = (const float*)d_in[3];
    const float* mask_b   = (const float*)d_in[4];
    const float* deform_w = (const float*)d_in[5];
    const float* deform_b = (const float*)d_in[6];
    float* out = (float*)d_out;

    cudaFuncSetAttribute(fused_kernel,
                         cudaFuncAttributeMaxDynamicSharedMemorySize, S_TOT);

    prep_w_kernel<<<(9 * 64 * 32 + 9 * 32 * 32 + 255) / 256, 256>>>(
        deform_w, offset_w, mask_w);

    dim3 grid(Hn, Bn);
    fused_kernel<<<grid, 128, S_TOT>>>(x, offset_b, mask_b, deform_b, out);
}

// round 11
// speedup vs baseline: 1.5380x; 1.5380x over previous
#include <cuda_runtime.h>
#include <cuda_bf16.h>
#include <stdint.h>
#include <math.h>

#define Bn 4
#define Cn 64
#define Hn 128
#define Wn 128
#define On 64
#define HW (Hn * Wn)

typedef unsigned long long ull;

// B weights pre-packed in MMA fragment order:
//   g_wB2[k][s][nt][lane] = uint4{ bh0, bh1, bl0, bl1 }  (deform, nt<8)
//   g_wA2[k][s][nt][lane] = same for offset/mask conv (nt<4, rows padded to 32)
__device__ __align__(16) uint4 g_wB2[9 * 4 * 8 * 32];   // 147456 B
__device__ __align__(16) uint4 g_wA2[9 * 4 * 4 * 32];   // 73728 B

// ---------------------------------------------------------------------------
// helpers
// ---------------------------------------------------------------------------
__device__ __forceinline__ uint32_t cvt_bf16x2(float lo, float hi) {
    uint32_t r;
    asm("cvt.rn.satfinite.bf16x2.f32 %0, %1, %2;" : "=r"(r) : "f"(hi), "f"(lo));
    return r;
}
__device__ __forceinline__ uint32_t smem_u32(const void* p) {
    uint32_t a;
    asm("{ .reg .u64 t; cvta.to.shared.u64 t, %1; cvt.u32.u64 %0, t; }"
        : "=r"(a) : "l"(p));
    return a;
}
__device__ __forceinline__ void sts128(uint32_t addr, const uint32_t* v) {
    asm volatile("st.shared.v4.b32 [%0], {%1,%2,%3,%4};"
                 :: "r"(addr), "r"(v[0]), "r"(v[1]), "r"(v[2]), "r"(v[3])
                 : "memory");
}
__device__ __forceinline__ float lds_f32(uint32_t addr) {
    float v; asm volatile("ld.shared.f32 %0, [%1];" : "=f"(v) : "r"(addr));
    return v;
}
__device__ __forceinline__ void sts_f32(uint32_t addr, float v) {
    asm volatile("st.shared.f32 [%0], %1;" :: "r"(addr), "f"(v) : "memory");
}
// ldmatrix x4: matrices in address order = mma A-frag order
// (m0-7/k0-7, m8-15/k0-7, m0-7/k8-15, m8-15/k8-15)
__device__ __forceinline__ void ldmA(uint32_t* a, uint32_t addr) {
    asm volatile("ldmatrix.sync.aligned.m8n8.x4.shared.b16 {%0,%1,%2,%3}, [%4];"
                 : "=r"(a[0]), "=r"(a[1]), "=r"(a[2]), "=r"(a[3]) : "r"(addr));
}
// m16n8k16 row.col bf16 -> fp32
__device__ __forceinline__ void mma16816(float* d, const uint32_t* a,
                                         uint32_t b0, uint32_t b1) {
    asm volatile(
        "mma.sync.aligned.m16n8k16.row.col.f32.bf16.bf16.f32 "
        "{%0,%1,%2,%3}, {%4,%5,%6,%7}, {%8,%9}, {%0,%1,%2,%3};"
        : "+f"(d[0]), "+f"(d[1]), "+f"(d[2]), "+f"(d[3])
        : "r"(a[0]), "r"(a[1]), "r"(a[2]), "r"(a[3]), "r"(b0), "r"(b1));
}
__device__ __forceinline__ void split2(float v0, float v1,
                                       uint32_t& hw, uint32_t& lw) {
    hw = cvt_bf16x2(v0, v1);
    float h0 = __uint_as_float(hw << 16);
    float h1 = __uint_as_float(hw & 0xFFFF0000u);
    lw = cvt_bf16x2(v0 - h0, v1 - h1);
}

// ---------------------------------------------------------------------------
// Kernel P: pack weights into fragment order.
// Fragment mapping (per k-step s): word0 = W[o = nt*8+lq][c0 = lr*2 + s*16, c0+1],
// word1 = channels c0+8, c0+9.  lq = lane>>2, lr = lane&3.
// ---------------------------------------------------------------------------
__global__ void prep_w_kernel(const float* __restrict__ dw,
                              const float* __restrict__ ow,
                              const float* __restrict__ mw) {
    int idx = blockIdx.x * blockDim.x + threadIdx.x;
    const int NB = 9 * 4 * 8 * 32;     // 9216
    const int NA = 9 * 4 * 4 * 32;     // 4608
    if (idx < NB) {
        int lane = idx & 31;
        int nt = (idx >> 5) & 7;
        int s  = (idx >> 8) & 3;
        int k  = idx >> 10;
        int o  = nt * 8 + (lane >> 2);
        int c0 = (lane & 3) * 2 + s * 16;
        uint32_t h0, l0, h1, l1;
        split2(dw[(o * Cn + c0) * 9 + k],     dw[(o * Cn + c0 + 1) * 9 + k], h0, l0);
        split2(dw[(o * Cn + c0 + 8) * 9 + k], dw[(o * Cn + c0 + 9) * 9 + k], h1, l1);
        g_wB2[idx] = make_uint4(h0, h1, l0, l1);
    } else if (idx < NB + NA) {
        int e = idx - NB;
        int lane = e & 31;
        int nt = (e >> 5) & 3;
        int s  = (e >> 7) & 3;
        int k  = e >> 9;
        int o  = nt * 8 + (lane >> 2);
        int c0 = (lane & 3) * 2 + s * 16;
        float wv[4] = {0.f, 0.f, 0.f, 0.f};
        if (o < 18) {
            wv[0] = ow[(o * Cn + c0) * 9 + k];
            wv[1] = ow[(o * Cn + c0 + 1) * 9 + k];
            wv[2] = ow[(o * Cn + c0 + 8) * 9 + k];
            wv[3] = ow[(o * Cn + c0 + 9) * 9 + k];
        } else if (o < 27) {
            int om = o - 18;
            wv[0] = mw[(om * Cn + c0) * 9 + k];
            wv[1] = mw[(om * Cn + c0 + 1) * 9 + k];
            wv[2] = mw[(om * Cn + c0 + 8) * 9 + k];
            wv[3] = mw[(om * Cn + c0 + 9) * 9 + k];
        }
        uint32_t h0, l0, h1, l1;
        split2(wv[0], wv[1], h0, l0);
        split2(wv[2], wv[3], h1, l1);
        g_wA2[e] = make_uint4(h0, h1, l0, l1);
    }
}

// ---------------------------------------------------------------------------
// Fused kernel, BARRIER-FREE: every data flow is warp-private.
//  - A tile rows [wrp*32, wrp*32+32) written by own threads, read via ldmatrix
//    by own warp only -> __syncwarp suffices.
//  - B fragments loaded per-warp directly from gmem (fragment-order, LDG.128).
//  - offset/mask handoff S_OFF is warp-private (pixel slices match).
// SW128: addr = row*128 + (colBytes ^ ((row&7)<<4)).
// ---------------------------------------------------------------------------
#define S_AH  0
#define S_AL  16384
#define S_OFF 32768               // 32 ch x 128 px floats (27 used)
#define S_TOT 49152

__global__ __launch_bounds__(128) void fused_kernel(
    const float* __restrict__ x,
    const float* __restrict__ offset_b,
    const float* __restrict__ mask_b,
    const float* __restrict__ deform_b,
    float* __restrict__ out)
{
    extern __shared__ char smem[];
    const uint32_t sb = smem_u32(smem);
    const int tid  = threadIdx.x;
    const int lane = tid & 31;
    const int wrp  = tid >> 5;
    const int h = blockIdx.x;
    const int b = blockIdx.y;

    const float* xb = x + (size_t)b * Cn * HW;

    const int lq = lane >> 2;              // 0..7
    const int lr = lane & 3;               // 0..3
    // ldmatrix lane roles
    const int g  = lane >> 3;              // 0..3
    const int r  = lane & 7;               // 0..7
    const uint32_t rsw   = (uint32_t)r << 4;
    const uint32_t kh16  = (uint32_t)(g >> 1) << 4;       // 0 or 16
    const uint32_t rowLd = (uint32_t)(wrp * 32 + (g & 1) * 8 + r) * 128;
    // gather write
    const uint32_t tsw    = (uint32_t)(tid & 7) << 4;
    const uint32_t rowoff = (uint32_t)tid * 128;

    // ======================= Phase 1: offset/mask conv ======================
    {
        float doff[2][4][4];
#pragma unroll
        for (int mt = 0; mt < 2; ++mt)
#pragma unroll
            for (int nt = 0; nt < 4; ++nt)
#pragma unroll
                for (int i = 0; i < 4; ++i) doff[mt][nt][i] = 0.f;

        for (int k = 0; k < 9; ++k) {
            __syncwarp();          // prev tap's ldmatrix done before overwrite
            int y  = h + k / 3 - 1;
            int xc = tid + k % 3 - 1;
            bool ok = (y >= 0) && (y < Hn) && (xc >= 0) && (xc < Wn);
            const float* xp = xb + y * Wn + xc;
#pragma unroll
            for (int q = 0; q < 8; ++q) {
                uint32_t hw4[4], lw4[4];
#pragma unroll
                for (int j = 0; j < 4; ++j) {
                    int c0 = q * 8 + j * 2;
                    float v0 = ok ? __ldg(xp + c0 * HW) : 0.f;
                    float v1 = ok ? __ldg(xp + (c0 + 1) * HW) : 0.f;
                    split2(v0, v1, hw4[j], lw4[j]);
                }
                uint32_t off = rowoff + (((uint32_t)(q * 16)) ^ tsw);
                sts128(sb + S_AH + off, hw4);
                sts128(sb + S_AL + off, lw4);
            }
            __syncwarp();
            const uint4* wB = g_wA2 + (k * 4) * 4 * 32 + lane;
#pragma unroll
            for (int s = 0; s < 4; ++s) {
                uint32_t kt = ((uint32_t)(s * 32) + kh16) ^ rsw;
                uint32_t ah[2][4], al[2][4];
#pragma unroll
                for (int mt = 0; mt < 2; ++mt) {
                    ldmA(ah[mt], sb + S_AH + rowLd + mt * 2048 + kt);
                    ldmA(al[mt], sb + S_AL + rowLd + mt * 2048 + kt);
                }
#pragma unroll
                for (int nt = 0; nt < 4; ++nt) {
                    uint4 bw = __ldg(&wB[(s * 4 + nt) * 32]);
#pragma unroll
                    for (int mt = 0; mt < 2; ++mt) {
                        mma16816(doff[mt][nt], ah[mt], bw.x, bw.y);
                        mma16816(doff[mt][nt], al[mt], bw.x, bw.y);
                        mma16816(doff[mt][nt], ah[mt], bw.z, bw.w);
                    }
                }
            }
        }
        // Epilogue: bias + sigmoid -> S_OFF (warp-private pixel slice)
#pragma unroll
        for (int nt = 0; nt < 4; ++nt) {
#pragma unroll
            for (int oi = 0; oi < 2; ++oi) {
                int o = nt * 8 + lr * 2 + oi;
                float bias = 0.f; bool sig = false;
                if (o < 18) bias = __ldg(offset_b + o);
                else if (o < 27) { bias = __ldg(mask_b + o - 18); sig = true; }
#pragma unroll
                for (int mt = 0; mt < 2; ++mt) {
                    int px0 = wrp * 32 + mt * 16 + lq;
#pragma unroll
                    for (int ri = 0; ri < 2; ++ri) {
                        float v = doff[mt][nt][ri * 2 + oi] + bias;
                        if (sig) v = 1.f / (1.f + __expf(-v));
                        sts_f32(sb + S_OFF + (uint32_t)(o * 128 + px0 + ri * 8) * 4, v);
                    }
                }
            }
        }
        __syncwarp();
    }

    // ========================= Phase 2: deform conv =========================
    float d[2][8][4];
#pragma unroll
    for (int mt = 0; mt < 2; ++mt)
#pragma unroll
        for (int nt = 0; nt < 8; ++nt)
#pragma unroll
            for (int i = 0; i < 4; ++i) d[mt][nt][i] = 0.f;

    for (int k = 0; k < 9; ++k) {
        __syncwarp();

        float dy = lds_f32(sb + S_OFF + (uint32_t)((2 * k) * 128 + tid) * 4);
        float dx = lds_f32(sb + S_OFF + (uint32_t)((2 * k + 1) * 128 + tid) * 4);
        float m  = lds_f32(sb + S_OFF + (uint32_t)((18 + k) * 128 + tid) * 4);

        float py = dy + (float)(k / 3 + h - 1);
        float px = dx + (float)(k % 3 + tid - 1);
        float y0f = floorf(py), x0f = floorf(px);
        float fy = py - y0f, fx = px - x0f;
        int y0 = (int)y0f, x0 = (int)x0f;
        int y1 = y0 + 1, x1 = x0 + 1;
        float wy0 = 1.f - fy, wx0 = 1.f - fx;
        float w00 = wy0 * wx0 * m;
        float w01 = wy0 * fx  * m;
        float w10 = fy  * wx0 * m;
        float w11 = fy  * fx  * m;
        bool vy0 = (y0 >= 0) && (y0 < Hn);
        bool vy1 = (y1 >= 0) && (y1 < Hn);
        bool vx0 = (x0 >= 0) && (x0 < Wn);
        bool vx1 = (x1 >= 0) && (x1 < Wn);
        if (!(vy0 && vx0)) w00 = 0.f;
        if (!(vy0 && vx1)) w01 = 0.f;
        if (!(vy1 && vx0)) w10 = 0.f;
        if (!(vy1 && vx1)) w11 = 0.f;
        int y0c = min(max(y0, 0), Hn - 1), y1c = min(max(y1, 0), Hn - 1);
        int x0c = min(max(x0, 0), Wn - 1), x1c = min(max(x1, 0), Wn - 1);
        int i00 = y0c * Wn + x0c, i01 = y0c * Wn + x1c;
        int i10 = y1c * Wn + x0c, i11 = y1c * Wn + x1c;

#pragma unroll
        for (int q = 0; q < 8; ++q) {
            uint32_t hw4[4], lw4[4];
#pragma unroll
            for (int j = 0; j < 4; ++j) {
                const float* xc0 = xb + (q * 8 + j * 2) * HW;
                const float* xc1 = xc0 + HW;
                float v0 = w00 * __ldg(xc0 + i00) + w01 * __ldg(xc0 + i01)
                         + w10 * __ldg(xc0 + i10) + w11 * __ldg(xc0 + i11);
                float v1 = w00 * __ldg(xc1 + i00) + w01 * __ldg(xc1 + i01)
                         + w10 * __ldg(xc1 + i10) + w11 * __ldg(xc1 + i11);
                split2(v0, v1, hw4[j], lw4[j]);
            }
            uint32_t off = rowoff + (((uint32_t)(q * 16)) ^ tsw);
            sts128(sb + S_AH + off, hw4);
            sts128(sb + S_AL + off, lw4);
        }
        __syncwarp();

        const uint4* wB = g_wB2 + (k * 4) * 8 * 32 + lane;
#pragma unroll
        for (int s = 0; s < 4; ++s) {
            uint32_t kt = ((uint32_t)(s * 32) + kh16) ^ rsw;
            uint32_t ah[2][4], al[2][4];
#pragma unroll
            for (int mt = 0; mt < 2; ++mt) {
                ldmA(ah[mt], sb + S_AH + rowLd + mt * 2048 + kt);
                ldmA(al[mt], sb + S_AL + rowLd + mt * 2048 + kt);
            }
#pragma unroll
            for (int nt = 0; nt < 8; ++nt) {
                uint4 bw = __ldg(&wB[(s * 8 + nt) * 32]);
#pragma unroll
                for (int mt = 0; mt < 2; ++mt) {
                    mma16816(d[mt][nt], ah[mt], bw.x, bw.y);
                    mma16816(d[mt][nt], al[mt], bw.x, bw.y);
                    mma16816(d[mt][nt], ah[mt], bw.z, bw.w);
                }
            }
        }
    }

    // epilogue: d[mt][nt][i] -> out[(b*64+o)*HW + h*Wn + px] + bias
#pragma unroll
    for (int nt = 0; nt < 8; ++nt) {
        int o0 = nt * 8 + lr * 2;
        float bb0 = __ldg(deform_b + o0);
        float bb1 = __ldg(deform_b + o0 + 1);
#pragma unroll
        for (int mt = 0; mt < 2; ++mt) {
            int px0 = wrp * 32 + mt * 16 + lq;
            float* o0p = out + ((size_t)(b * On + o0)) * HW + h * Wn;
            float* o1p = o0p + HW;
            o0p[px0]     = d[mt][nt][0] + bb0;
            o1p[px0]     = d[mt][nt][1] + bb1;
            o0p[px0 + 8] = d[mt][nt][2] + bb0;
            o1p[px0 + 8] = d[mt][nt][3] + bb1;
        }
    }
}

// ---------------------------------------------------------------------------
extern "C" void kernel_launch(void* const* d_in, const int* in_sizes, int n_in,
                              void* d_out, int out_size) {
    const float* x        = (const float*)d_in[0];
    const float* offset_w = (const float*)d_in[1];
    const float* offset_b = (const float*)d_in[2];
    const float* mask_w   = (const float*)d_in[3];
    const float* mask_b   = (const float*)d_in[4];
    const float* deform_w = (const float*)d_in[5];
    const float* deform_b = (const float*)d_in[6];
    float* out = (float*)d_out;

    cudaFuncSetAttribute(fused_kernel,
                         cudaFuncAttributeMaxDynamicSharedMemorySize, S_TOT);

    prep_w_kernel<<<(9 * 4 * 8 * 32 + 9 * 4 * 4 * 32 + 255) / 256, 256>>>(
        deform_w, offset_w, mask_w);

    dim3 grid(Hn, Bn);
    fused_kernel<<<grid, 128, S_TOT>>>(x, offset_b, mask_b, deform_b, out);
}

// round 14
// speedup vs baseline: 1.7329x; 1.1267x over previous
#include <cuda_runtime.h>
#include <cuda_bf16.h>
#include <stdint.h>
#include <math.h>

#define Bn 4
#define Cn 64
#define Hn 128
#define Wn 128
#define On 64
#define HW (Hn * Wn)

typedef unsigned long long ull;

// B weights pre-packed in MMA fragment order:
//   g_wB2[k][s][nt][lane] = uint4{ bh0, bh1, bl0, bl1 }  (deform, nt<8)
//   g_wA2[k][s][nt][lane] = same for offset/mask conv (nt<4, rows padded to 32)
__device__ __align__(16) uint4 g_wB2[9 * 4 * 8 * 32];   // 147456 B
__device__ __align__(16) uint4 g_wA2[9 * 4 * 4 * 32];   // 73728 B

// ---------------------------------------------------------------------------
// helpers
// ---------------------------------------------------------------------------
__device__ __forceinline__ uint32_t cvt_bf16x2(float lo, float hi) {
    uint32_t r;
    asm("cvt.rn.satfinite.bf16x2.f32 %0, %1, %2;" : "=r"(r) : "f"(hi), "f"(lo));
    return r;
}
__device__ __forceinline__ uint32_t smem_u32(const void* p) {
    uint32_t a;
    asm("{ .reg .u64 t; cvta.to.shared.u64 t, %1; cvt.u32.u64 %0, t; }"
        : "=r"(a) : "l"(p));
    return a;
}
__device__ __forceinline__ void sts128(uint32_t addr, const uint32_t* v) {
    asm volatile("st.shared.v4.b32 [%0], {%1,%2,%3,%4};"
                 :: "r"(addr), "r"(v[0]), "r"(v[1]), "r"(v[2]), "r"(v[3])
                 : "memory");
}
__device__ __forceinline__ float lds_f32(uint32_t addr) {
    float v; asm volatile("ld.shared.f32 %0, [%1];" : "=f"(v) : "r"(addr));
    return v;
}
__device__ __forceinline__ void sts_f32(uint32_t addr, float v) {
    asm volatile("st.shared.f32 [%0], %1;" :: "r"(addr), "f"(v) : "memory");
}
// ldmatrix x4: matrices in address order = mma A-frag order
__device__ __forceinline__ void ldmA(uint32_t* a, uint32_t addr) {
    asm volatile("ldmatrix.sync.aligned.m8n8.x4.shared.b16 {%0,%1,%2,%3}, [%4];"
                 : "=r"(a[0]), "=r"(a[1]), "=r"(a[2]), "=r"(a[3]) : "r"(addr));
}
// m16n8k16 row.col bf16 -> fp32
__device__ __forceinline__ void mma16816(float* d, const uint32_t* a,
                                         uint32_t b0, uint32_t b1) {
    asm volatile(
        "mma.sync.aligned.m16n8k16.row.col.f32.bf16.bf16.f32 "
        "{%0,%1,%2,%3}, {%4,%5,%6,%7}, {%8,%9}, {%0,%1,%2,%3};"
        : "+f"(d[0]), "+f"(d[1]), "+f"(d[2]), "+f"(d[3])
        : "r"(a[0]), "r"(a[1]), "r"(a[2]), "r"(a[3]), "r"(b0), "r"(b1));
}
__device__ __forceinline__ void split2(float v0, float v1,
                                       uint32_t& hw, uint32_t& lw) {
    hw = cvt_bf16x2(v0, v1);
    float h0 = __uint_as_float(hw << 16);
    float h1 = __uint_as_float(hw & 0xFFFF0000u);
    lw = cvt_bf16x2(v0 - h0, v1 - h1);
}

// ---------------------------------------------------------------------------
// Kernel P: pack weights into fragment order (unchanged from R11).
// ---------------------------------------------------------------------------
__global__ void prep_w_kernel(const float* __restrict__ dw,
                              const float* __restrict__ ow,
                              const float* __restrict__ mw) {
    int idx = blockIdx.x * blockDim.x + threadIdx.x;
    const int NB = 9 * 4 * 8 * 32;     // 9216
    const int NA = 9 * 4 * 4 * 32;     // 4608
    if (idx < NB) {
        int lane = idx & 31;
        int nt = (idx >> 5) & 7;
        int s  = (idx >> 8) & 3;
        int k  = idx >> 10;
        int o  = nt * 8 + (lane >> 2);
        int c0 = (lane & 3) * 2 + s * 16;
        uint32_t h0, l0, h1, l1;
        split2(dw[(o * Cn + c0) * 9 + k],     dw[(o * Cn + c0 + 1) * 9 + k], h0, l0);
        split2(dw[(o * Cn + c0 + 8) * 9 + k], dw[(o * Cn + c0 + 9) * 9 + k], h1, l1);
        g_wB2[idx] = make_uint4(h0, h1, l0, l1);
    } else if (idx < NB + NA) {
        int e = idx - NB;
        int lane = e & 31;
        int nt = (e >> 5) & 3;
        int s  = (e >> 7) & 3;
        int k  = e >> 9;
        int o  = nt * 8 + (lane >> 2);
        int c0 = (lane & 3) * 2 + s * 16;
        float wv[4] = {0.f, 0.f, 0.f, 0.f};
        if (o < 18) {
            wv[0] = ow[(o * Cn + c0) * 9 + k];
            wv[1] = ow[(o * Cn + c0 + 1) * 9 + k];
            wv[2] = ow[(o * Cn + c0 + 8) * 9 + k];
            wv[3] = ow[(o * Cn + c0 + 9) * 9 + k];
        } else if (o < 27) {
            int om = o - 18;
            wv[0] = mw[(om * Cn + c0) * 9 + k];
            wv[1] = mw[(om * Cn + c0 + 1) * 9 + k];
            wv[2] = mw[(om * Cn + c0 + 8) * 9 + k];
            wv[3] = mw[(om * Cn + c0 + 9) * 9 + k];
        }
        uint32_t h0, l0, h1, l1;
        split2(wv[0], wv[1], h0, l0);
        split2(wv[2], wv[3], h1, l1);
        g_wA2[e] = make_uint4(h0, h1, l0, l1);
    }
}

// ---------------------------------------------------------------------------
// Fused kernel, 64-thread blocks (2 warps, 64 pixels), BARRIER-FREE.
// blockIdx.x = h*2 + seg; block covers pixels [seg*64, seg*64+64) of row h.
// All dataflow warp-private (A rows, S_OFF slices). 7 blocks/SM -> 14 warps,
// grid 1024 fits one wave (148*7 = 1036).
// SW128: addr = row*128 + (colBytes ^ ((row&7)<<4)).
// ---------------------------------------------------------------------------
#define S_AH  0
#define S_AL  8192
#define S_OFF 16384               // 32 ch x 64 px floats (27 used)
#define S_TOT 24576

__global__ __launch_bounds__(64, 7) void fused_kernel(
    const float* __restrict__ x,
    const float* __restrict__ offset_b,
    const float* __restrict__ mask_b,
    const float* __restrict__ deform_b,
    float* __restrict__ out)
{
    extern __shared__ char smem[];
    const uint32_t sb = smem_u32(smem);
    const int tid  = threadIdx.x;          // 0..63
    const int lane = tid & 31;
    const int wrp  = tid >> 5;             // 0..1
    const int h   = blockIdx.x >> 1;
    const int col0 = (blockIdx.x & 1) * 64;   // pixel-column base of this block
    const int b = blockIdx.y;

    const float* xb = x + (size_t)b * Cn * HW;

    const int lq = lane >> 2;              // 0..7
    const int lr = lane & 3;               // 0..3
    // ldmatrix lane roles
    const int g  = lane >> 3;              // 0..3
    const int r  = lane & 7;               // 0..7
    const uint32_t rsw   = (uint32_t)r << 4;
    const uint32_t kh16  = (uint32_t)(g >> 1) << 4;       // 0 or 16
    const uint32_t rowLd = (uint32_t)(wrp * 32 + (g & 1) * 8 + r) * 128;
    // gather write
    const uint32_t tsw    = (uint32_t)(tid & 7) << 4;
    const uint32_t rowoff = (uint32_t)tid * 128;

    // ======================= Phase 1: offset/mask conv ======================
    {
        float doff[2][4][4];
#pragma unroll
        for (int mt = 0; mt < 2; ++mt)
#pragma unroll
            for (int nt = 0; nt < 4; ++nt)
#pragma unroll
                for (int i = 0; i < 4; ++i) doff[mt][nt][i] = 0.f;

        for (int k = 0; k < 9; ++k) {
            __syncwarp();          // prev tap's ldmatrix done before overwrite
            int y  = h + k / 3 - 1;
            int xc = col0 + tid + k % 3 - 1;
            bool ok = (y >= 0) && (y < Hn) && (xc >= 0) && (xc < Wn);
            const float* xp = xb + y * Wn + xc;
#pragma unroll
            for (int q = 0; q < 8; ++q) {
                uint32_t hw4[4], lw4[4];
#pragma unroll
                for (int j = 0; j < 4; ++j) {
                    int c0 = q * 8 + j * 2;
                    float v0 = ok ? __ldg(xp + c0 * HW) : 0.f;
                    float v1 = ok ? __ldg(xp + (c0 + 1) * HW) : 0.f;
                    split2(v0, v1, hw4[j], lw4[j]);
                }
                uint32_t off = rowoff + (((uint32_t)(q * 16)) ^ tsw);
                sts128(sb + S_AH + off, hw4);
                sts128(sb + S_AL + off, lw4);
            }
            __syncwarp();
            const uint4* wB = g_wA2 + (k * 4) * 4 * 32 + lane;
#pragma unroll
            for (int s = 0; s < 4; ++s) {
                uint32_t kt = ((uint32_t)(s * 32) + kh16) ^ rsw;
                uint32_t ah[2][4], al[2][4];
#pragma unroll
                for (int mt = 0; mt < 2; ++mt) {
                    ldmA(ah[mt], sb + S_AH + rowLd + mt * 2048 + kt);
                    ldmA(al[mt], sb + S_AL + rowLd + mt * 2048 + kt);
                }
#pragma unroll
                for (int nt = 0; nt < 4; ++nt) {
                    uint4 bw = __ldg(&wB[(s * 4 + nt) * 32]);
#pragma unroll
                    for (int mt = 0; mt < 2; ++mt) {
                        mma16816(doff[mt][nt], ah[mt], bw.x, bw.y);
                        mma16816(doff[mt][nt], al[mt], bw.x, bw.y);
                        mma16816(doff[mt][nt], ah[mt], bw.z, bw.w);
                    }
                }
            }
        }
        // Epilogue: bias + sigmoid -> S_OFF (warp-private pixel slice)
#pragma unroll
        for (int nt = 0; nt < 4; ++nt) {
#pragma unroll
            for (int oi = 0; oi < 2; ++oi) {
                int o = nt * 8 + lr * 2 + oi;
                float bias = 0.f; bool sig = false;
                if (o < 18) bias = __ldg(offset_b + o);
                else if (o < 27) { bias = __ldg(mask_b + o - 18); sig = true; }
#pragma unroll
                for (int mt = 0; mt < 2; ++mt) {
                    int px0 = wrp * 32 + mt * 16 + lq;
#pragma unroll
                    for (int ri = 0; ri < 2; ++ri) {
                        float v = doff[mt][nt][ri * 2 + oi] + bias;
                        if (sig) v = 1.f / (1.f + __expf(-v));
                        sts_f32(sb + S_OFF + (uint32_t)(o * 64 + px0 + ri * 8) * 4, v);
                    }
                }
            }
        }
        __syncwarp();
    }

    // ========================= Phase 2: deform conv =========================
    float d[2][8][4];
#pragma unroll
    for (int mt = 0; mt < 2; ++mt)
#pragma unroll
        for (int nt = 0; nt < 8; ++nt)
#pragma unroll
            for (int i = 0; i < 4; ++i) d[mt][nt][i] = 0.f;

    for (int k = 0; k < 9; ++k) {
        __syncwarp();

        float dy = lds_f32(sb + S_OFF + (uint32_t)((2 * k) * 64 + tid) * 4);
        float dx = lds_f32(sb + S_OFF + (uint32_t)((2 * k + 1) * 64 + tid) * 4);
        float m  = lds_f32(sb + S_OFF + (uint32_t)((18 + k) * 64 + tid) * 4);

        float py = dy + (float)(k / 3 + h - 1);
        float px = dx + (float)(k % 3 + col0 + tid - 1);
        float y0f = floorf(py), x0f = floorf(px);
        float fy = py - y0f, fx = px - x0f;
        int y0 = (int)y0f, x0 = (int)x0f;
        int y1 = y0 + 1, x1 = x0 + 1;
        float wy0 = 1.f - fy, wx0 = 1.f - fx;
        float w00 = wy0 * wx0 * m;
        float w01 = wy0 * fx  * m;
        float w10 = fy  * wx0 * m;
        float w11 = fy  * fx  * m;
        bool vy0 = (y0 >= 0) && (y0 < Hn);
        bool vy1 = (y1 >= 0) && (y1 < Hn);
        bool vx0 = (x0 >= 0) && (x0 < Wn);
        bool vx1 = (x1 >= 0) && (x1 < Wn);
        if (!(vy0 && vx0)) w00 = 0.f;
        if (!(vy0 && vx1)) w01 = 0.f;
        if (!(vy1 && vx0)) w10 = 0.f;
        if (!(vy1 && vx1)) w11 = 0.f;
        int y0c = min(max(y0, 0), Hn - 1), y1c = min(max(y1, 0), Hn - 1);
        int x0c = min(max(x0, 0), Wn - 1), x1c = min(max(x1, 0), Wn - 1);
        int i00 = y0c * Wn + x0c, i01 = y0c * Wn + x1c;
        int i10 = y1c * Wn + x0c, i11 = y1c * Wn + x1c;

#pragma unroll
        for (int q = 0; q < 8; ++q) {
            uint32_t hw4[4], lw4[4];
#pragma unroll
            for (int j = 0; j < 4; ++j) {
                const float* xc0 = xb + (q * 8 + j * 2) * HW;
                const float* xc1 = xc0 + HW;
                float v0 = w00 * __ldg(xc0 + i00) + w01 * __ldg(xc0 + i01)
                         + w10 * __ldg(xc0 + i10) + w11 * __ldg(xc0 + i11);
                float v1 = w00 * __ldg(xc1 + i00) + w01 * __ldg(xc1 + i01)
                         + w10 * __ldg(xc1 + i10) + w11 * __ldg(xc1 + i11);
                split2(v0, v1, hw4[j], lw4[j]);
            }
            uint32_t off = rowoff + (((uint32_t)(q * 16)) ^ tsw);
            sts128(sb + S_AH + off, hw4);
            sts128(sb + S_AL + off, lw4);
        }
        __syncwarp();

        const uint4* wB = g_wB2 + (k * 4) * 8 * 32 + lane;
#pragma unroll
        for (int s = 0; s < 4; ++s) {
            uint32_t kt = ((uint32_t)(s * 32) + kh16) ^ rsw;
            uint32_t ah[2][4], al[2][4];
#pragma unroll
            for (int mt = 0; mt < 2; ++mt) {
                ldmA(ah[mt], sb + S_AH + rowLd + mt * 2048 + kt);
                ldmA(al[mt], sb + S_AL + rowLd + mt * 2048 + kt);
            }
#pragma unroll
            for (int nt = 0; nt < 8; ++nt) {
                uint4 bw = __ldg(&wB[(s * 8 + nt) * 32]);
#pragma unroll
                for (int mt = 0; mt < 2; ++mt) {
                    mma16816(d[mt][nt], ah[mt], bw.x, bw.y);
                    mma16816(d[mt][nt], al[mt], bw.x, bw.y);
                    mma16816(d[mt][nt], ah[mt], bw.z, bw.w);
                }
            }
        }
    }

    // epilogue: d[mt][nt][i] -> out[(b*64+o)*HW + h*Wn + col0 + px] + bias
#pragma unroll
    for (int nt = 0; nt < 8; ++nt) {
        int o0 = nt * 8 + lr * 2;
        float bb0 = __ldg(deform_b + o0);
        float bb1 = __ldg(deform_b + o0 + 1);
#pragma unroll
        for (int mt = 0; mt < 2; ++mt) {
            int px0 = wrp * 32 + mt * 16 + lq;
            float* o0p = out + ((size_t)(b * On + o0)) * HW + h * Wn + col0;
            float* o1p = o0p + HW;
            o0p[px0]     = d[mt][nt][0] + bb0;
            o1p[px0]     = d[mt][nt][1] + bb1;
            o0p[px0 + 8] = d[mt][nt][2] + bb0;
            o1p[px0 + 8] = d[mt][nt][3] + bb1;
        }
    }
}

// ---------------------------------------------------------------------------
extern "C" void kernel_launch(void* const* d_in, const int* in_sizes, int n_in,
                              void* d_out, int out_size) {
    const float* x        = (const float*)d_in[0];
    const float* offset_w = (const float*)d_in[1];
    const float* offset_b = (const float*)d_in[2];
    const float* mask_w   = (const float*)d_in[3];
    const float* mask_b   = (const float*)d_in[4];
    const float* deform_w = (const float*)d_in[5];
    const float* deform_b = (const float*)d_in[6];
    float* out = (float*)d_out;

    cudaFuncSetAttribute(fused_kernel,
                         cudaFuncAttributeMaxDynamicSharedMemorySize, S_TOT);

    prep_w_kernel<<<(9 * 4 * 8 * 32 + 9 * 4 * 4 * 32 + 255) / 256, 256>>>(
        deform_w, offset_w, mask_w);

    dim3 grid(Hn * 2, Bn);
    fused_kernel<<<grid, 64, S_TOT>>>(x, offset_b, mask_b, deform_b, out);
}